// round 9
// baseline (speedup 1.0000x reference)
#include <cuda_runtime.h>

#define B_TOTAL 2048
#define NPTS    256

__device__ float g_partial[B_TOTAL];
__device__ int   g_ctr;    // zero-init; last block resets it each run

// One warp per batch. blockDim = 32, grid = 2048.
// Point k = 8*lane + slot (true input index -> tie-break matches ref).
// Two targets per iteration; rare warp-uniform fallback when target j+1's
// argmin is the point target j just consumed.
__global__ __launch_bounds__(32) void match_kernel(const float* __restrict__ inp,
                                                   const float* __restrict__ tgt,
                                                   float* __restrict__ out) {
    const int lane = threadIdx.x;
    const int b = blockIdx.x;

    __shared__ float s_tgt[2 * NPTS];   // holds (-2x, -2y) pre-scaled targets
    // Stride 10 floats (40 B)/lane: float2 accesses 8B-aligned, LDS.64
    // two-phase bank pattern (10*lane mod 32 over 16 lanes) conflict-free.
    __shared__ float s_c[10 * 32];

    // Stage targets pre-scaled by -2 (coalesced float4); sum |t|^2 from raw.
    const float4* tg4 = (const float4*)(tgt + (size_t)b * 2 * NPTS);
    float4* st4 = (float4*)s_tgt;
    float tts = 0.0f;
    #pragma unroll
    for (int i = 0; i < 4; i++) {
        float4 v = tg4[lane + 32 * i];
        tts += fmaf(v.x, v.x, v.y * v.y) + fmaf(v.z, v.z, v.w * v.w);
        st4[lane + 32 * i] = make_float4(-2.0f * v.x, -2.0f * v.y,
                                         -2.0f * v.z, -2.0f * v.w);
    }

    // Own 8 consecutive points (coalesced float4): k = 8*lane + i.
    float px[8], py[8];
    const float4* in4 = (const float4*)(inp + (size_t)b * 2 * NPTS);
    #pragma unroll
    for (int p = 0; p < 4; p++) {
        float4 v = in4[4 * lane + p];
        px[2 * p]     = v.x;  py[2 * p]     = v.y;
        px[2 * p + 1] = v.z;  py[2 * p + 1] = v.w;
    }
    // c[i] = |p|^2 + 64  (+64 keeps d positive so uint-min == float-min);
    // becomes 1e30 once the point is used.
    #pragma unroll
    for (int i = 0; i < 8; i++)
        s_c[10 * lane + i] = fmaf(px[i], px[i], fmaf(py[i], py[i], 64.0f));

    __syncwarp();

    const float4* st4r = (const float4*)s_tgt;  // two pre-scaled targets each
    float acc = 0.0f;   // uniform across lanes

    #pragma unroll 2
    for (int jj = 0; jj < NPTS / 2; jj++) {
        float4 t01 = st4r[jj];   // (ax, ay, bx, by) already scaled by -2

        // c loaded once per pair, shared by both targets; stays live for
        // the fallback path.
        float c[8];
        #pragma unroll
        for (int p = 0; p < 4; p++) {
            float2 cc = *(const float2*)&s_c[10 * lane + 2 * p];
            c[2 * p] = cc.x;  c[2 * p + 1] = cc.y;
        }

        // Running mins (no key arrays -> no spills).
        // d = |t-p|^2 - |t|^2 + 64 > 0; key = (d_bits & ~0xFF) | k.
        unsigned l0 = 0xFFFFFFFFu, l1 = 0xFFFFFFFFu;
        #pragma unroll
        for (int i = 0; i < 8; i++) {
            unsigned kk = 8u * (unsigned)lane + (unsigned)i;
            float d0 = fmaf(t01.x, px[i], fmaf(t01.y, py[i], c[i]));
            float d1 = fmaf(t01.z, px[i], fmaf(t01.w, py[i], c[i]));
            l0 = min(l0, (__float_as_uint(d0) & 0xFFFFFF00u) | kk);
            l1 = min(l1, (__float_as_uint(d1) & 0xFFFFFF00u) | kk);
        }
        unsigned kw0 = __reduce_min_sync(0xFFFFFFFFu, l0);
        unsigned kw1 = __reduce_min_sync(0xFFFFFFFFu, l1);

        // Kill target0's winner.
        unsigned p0 = kw0 & 0xFFu;
        if ((p0 >> 3) == (unsigned)lane)
            s_c[10 * lane + (p0 & 7u)] = 1e30f;

        // Rare fallback (~2%): target1 wanted target0's point. Recompute
        // target1's keys from live regs, excluding the consumed slot.
        // (Removing a non-winning element never changes a min, so otherwise
        //  kw1 is already the correct post-kill argmin.)
        if (((kw0 ^ kw1) & 0xFFu) == 0u) {
            unsigned excl = ((p0 >> 3) == (unsigned)lane) ? (p0 & 7u) : 8u;
            l1 = 0xFFFFFFFFu;
            #pragma unroll
            for (int i = 0; i < 8; i++) {
                unsigned kk = 8u * (unsigned)lane + (unsigned)i;
                float d1 = fmaf(t01.z, px[i], fmaf(t01.w, py[i], c[i]));
                unsigned key = (__float_as_uint(d1) & 0xFFFFFF00u) | kk;
                l1 = min(l1, (excl == (unsigned)i) ? 0xFFFFFFFFu : key);
            }
            kw1 = __reduce_min_sync(0xFFFFFFFFu, l1);
        }

        // Kill target1's winner.
        unsigned p1 = kw1 & 0xFFu;
        if ((p1 >> 3) == (unsigned)lane)
            s_c[10 * lane + (p1 & 7u)] = 1e30f;

        // Uniform accumulate: truncated d + half-quantum de-bias (2^(e-16)).
        float dec0 = __uint_as_float(kw0 & 0xFFFFFF00u);
        float hq0  = __uint_as_float(kw0 & 0x7F800000u) * (1.0f / 65536.0f);
        float dec1 = __uint_as_float(kw1 & 0xFFFFFF00u);
        float hq1  = __uint_as_float(kw1 & 0x7F800000u) * (1.0f / 65536.0f);
        acc += (dec0 + hq0) + (dec1 + hq1);

        __syncwarp();   // kills visible before next iteration's c load
    }

    // Sum of |t|^2 over the batch (warp butterfly, off critical path).
    #pragma unroll
    for (int off = 16; off; off >>= 1)
        tts += __shfl_xor_sync(0xffffffffu, tts, off);

    // se_j = d_j - 64 + |t_j|^2  =>  batch sum = acc + tts - 64*256
    if (lane == 0) g_partial[b] = acc + tts - 64.0f * NPTS;
    __threadfence();

    // Fused deterministic final reduction (last block, fixed order, fp64).
    int last = 0;
    if (lane == 0) last = (atomicAdd(&g_ctr, 1) == B_TOTAL - 1);
    last = __shfl_sync(0xffffffffu, last, 0);
    if (last) {
        __threadfence();
        double s = 0.0;
        #pragma unroll
        for (int i = 0; i < B_TOTAL / 32; i++)
            s += (double)g_partial[lane + 32 * i];
        #pragma unroll
        for (int off = 16; off; off >>= 1)
            s += __shfl_xor_sync(0xffffffffu, s, off);
        if (lane == 0) {
            out[0] = (float)(s / (double)B_TOTAL / (double)(2 * NPTS));
            g_ctr = 0;                  // reset for next graph replay
        }
    }
}

extern "C" void kernel_launch(void* const* d_in, const int* in_sizes, int n_in,
                              void* d_out, int out_size) {
    const float* inp = (const float*)d_in[0];   // "input"
    const float* tgt = (const float*)d_in[1];   // "targets"
    match_kernel<<<B_TOTAL, 32>>>(inp, tgt, (float*)d_out);
}

// round 10
// speedup vs baseline: 1.1380x; 1.1380x over previous
#include <cuda_runtime.h>

#define B_TOTAL 2048
#define NPTS    256

typedef unsigned long long ull;

__device__ float g_partial[B_TOTAL];
__device__ int   g_ctr;    // zero-init; last block resets it each run

__device__ __forceinline__ ull pk2(float lo, float hi) {
    ull r; asm("mov.b64 %0, {%1, %2};" : "=l"(r) : "f"(lo), "f"(hi)); return r;
}
// Packed 2-wide fp32 FMA (sm_103a FFMA2; only reachable via PTX f32x2).
__device__ __forceinline__ ull ffma2(ull a, ull b, ull c) {
    ull d; asm("fma.rn.f32x2 %0, %1, %2, %3;" : "=l"(d) : "l"(a), "l"(b), "l"(c));
    return d;
}
__device__ __forceinline__ unsigned lo32(ull v) { return (unsigned)v; }
__device__ __forceinline__ unsigned hi32(ull v) { return (unsigned)(v >> 32); }

// One warp per batch. blockDim = 32, grid = 2048.
// Point k = 8*lane + slot (true input index -> tie-break matches ref).
// Two targets per iteration; rare warp-uniform fallback when target j+1's
// argmin is the point target j just consumed.
__global__ __launch_bounds__(32) void match_kernel(const float* __restrict__ inp,
                                                   const float* __restrict__ tgt,
                                                   float* __restrict__ out) {
    const int lane = threadIdx.x;
    const int b = blockIdx.x;

    // Each target j stored as (-2x, -2x, -2y, -2y): one broadcast LDS.128
    // yields both packed f32x2 coefficient registers.
    __shared__ float4 s_tgt4[NPTS];
    // Stride 10 floats (40 B)/lane: 8B-aligned pair loads, conflict-free.
    __shared__ float s_c[10 * 32];

    // Stage targets; sum |t|^2 from raw values.
    const float4* tg4 = (const float4*)(tgt + (size_t)b * 2 * NPTS);
    float tts = 0.0f;
    #pragma unroll
    for (int i = 0; i < 4; i++) {
        float4 v = tg4[lane + 32 * i];      // targets 2*(lane+32i), +1
        tts += fmaf(v.x, v.x, v.y * v.y) + fmaf(v.z, v.z, v.w * v.w);
        int t0 = 2 * (lane + 32 * i);
        s_tgt4[t0]     = make_float4(-2.0f * v.x, -2.0f * v.x,
                                     -2.0f * v.y, -2.0f * v.y);
        s_tgt4[t0 + 1] = make_float4(-2.0f * v.z, -2.0f * v.z,
                                     -2.0f * v.w, -2.0f * v.w);
    }

    // Own 8 consecutive points (coalesced float4): k = 8*lane + i.
    // Keep coordinates as packed f32x2 pairs (points 2p, 2p+1).
    ull px2[4], py2[4];
    unsigned kk[8];
    const float4* in4 = (const float4*)(inp + (size_t)b * 2 * NPTS);
    #pragma unroll
    for (int p = 0; p < 4; p++) {
        float4 v = in4[4 * lane + p];       // (x2p, y2p, x2p+1, y2p+1)
        px2[p] = pk2(v.x, v.z);
        py2[p] = pk2(v.y, v.w);
        // c = |p|^2 + 64 (keeps d positive so uint-min == float-min);
        // becomes 1e30 once used.
        s_c[10 * lane + 2 * p]     = fmaf(v.x, v.x, fmaf(v.y, v.y, 64.0f));
        s_c[10 * lane + 2 * p + 1] = fmaf(v.z, v.z, fmaf(v.w, v.w, 64.0f));
        kk[2 * p]     = 8u * (unsigned)lane + 2u * p;
        kk[2 * p + 1] = 8u * (unsigned)lane + 2u * p + 1u;
    }

    __syncwarp();

    float acc = 0.0f;   // uniform across lanes

    #pragma unroll 2
    for (int jj = 0; jj < NPTS / 2; jj++) {
        float4 ta = s_tgt4[2 * jj];         // (-2x,-2x,-2y,-2y) target 2jj
        float4 tb = s_tgt4[2 * jj + 1];     // target 2jj+1
        ull ax2 = pk2(ta.x, ta.y), ay2 = pk2(ta.z, ta.w);
        ull bx2 = pk2(tb.x, tb.y), by2 = pk2(tb.z, tb.w);

        // c pairs loaded once, shared by both targets; live for fallback.
        ull c2[4];
        #pragma unroll
        for (int p = 0; p < 4; p++)
            c2[p] = *(const ull*)&s_c[10 * lane + 2 * p];

        // d = |t-p|^2 - |t|^2 + 64 > 0, two points per FFMA2 chain.
        // key = (d_bits & ~0xFF) | k; running u32 min.
        unsigned l0 = 0xFFFFFFFFu, l1 = 0xFFFFFFFFu;
        #pragma unroll
        for (int p = 0; p < 4; p++) {
            ull d0 = ffma2(ax2, px2[p], ffma2(ay2, py2[p], c2[p]));
            ull d1 = ffma2(bx2, px2[p], ffma2(by2, py2[p], c2[p]));
            l0 = min(l0, (lo32(d0) & 0xFFFFFF00u) | kk[2 * p]);
            l0 = min(l0, (hi32(d0) & 0xFFFFFF00u) | kk[2 * p + 1]);
            l1 = min(l1, (lo32(d1) & 0xFFFFFF00u) | kk[2 * p]);
            l1 = min(l1, (hi32(d1) & 0xFFFFFF00u) | kk[2 * p + 1]);
        }
        unsigned kw0 = __reduce_min_sync(0xFFFFFFFFu, l0);
        unsigned kw1 = __reduce_min_sync(0xFFFFFFFFu, l1);

        // Kill target0's winner.
        unsigned p0 = kw0 & 0xFFu;
        if ((p0 >> 3) == (unsigned)lane)
            s_c[10 * lane + (p0 & 7u)] = 1e30f;

        // Rare fallback (~2%): target1 wanted target0's point. Scalar
        // recompute from live regs, excluding the consumed slot.
        if (((kw0 ^ kw1) & 0xFFu) == 0u) {
            unsigned excl = ((p0 >> 3) == (unsigned)lane) ? (p0 & 7u) : 8u;
            float bx = tb.x, by = tb.z;
            l1 = 0xFFFFFFFFu;
            #pragma unroll
            for (int p = 0; p < 4; p++) {
                float cx = __uint_as_float(lo32(c2[p]));
                float cy = __uint_as_float(hi32(c2[p]));
                float pxl = __uint_as_float(lo32(px2[p]));
                float pxh = __uint_as_float(hi32(px2[p]));
                float pyl = __uint_as_float(lo32(py2[p]));
                float pyh = __uint_as_float(hi32(py2[p]));
                float dl = fmaf(bx, pxl, fmaf(by, pyl, cx));
                float dh = fmaf(bx, pxh, fmaf(by, pyh, cy));
                unsigned kl = (__float_as_uint(dl) & 0xFFFFFF00u) | kk[2 * p];
                unsigned kh = (__float_as_uint(dh) & 0xFFFFFF00u) | kk[2 * p + 1];
                l1 = min(l1, (excl == 2u * p)      ? 0xFFFFFFFFu : kl);
                l1 = min(l1, (excl == 2u * p + 1u) ? 0xFFFFFFFFu : kh);
            }
            kw1 = __reduce_min_sync(0xFFFFFFFFu, l1);
        }

        // Kill target1's winner.
        unsigned p1 = kw1 & 0xFFu;
        if ((p1 >> 3) == (unsigned)lane)
            s_c[10 * lane + (p1 & 7u)] = 1e30f;

        // Uniform accumulate. Index bits sit at denormal magnitude vs d>=38
        // and 8-bit truncation bias is ~2^-16 relative: both negligible.
        acc += __uint_as_float(kw0) + __uint_as_float(kw1);

        __syncwarp();   // kills visible before next iteration's c load
    }

    // Sum of |t|^2 over the batch (warp butterfly, off critical path).
    #pragma unroll
    for (int off = 16; off; off >>= 1)
        tts += __shfl_xor_sync(0xffffffffu, tts, off);

    // se_j = d_j - 64 + |t_j|^2  =>  batch sum = acc + tts - 64*256
    if (lane == 0) g_partial[b] = acc + tts - 64.0f * NPTS;
    __threadfence();

    // Fused deterministic final reduction (last block, fixed order, fp64).
    int last = 0;
    if (lane == 0) last = (atomicAdd(&g_ctr, 1) == B_TOTAL - 1);
    last = __shfl_sync(0xffffffffu, last, 0);
    if (last) {
        __threadfence();
        double s = 0.0;
        #pragma unroll
        for (int i = 0; i < B_TOTAL / 32; i++)
            s += (double)g_partial[lane + 32 * i];
        #pragma unroll
        for (int off = 16; off; off >>= 1)
            s += __shfl_xor_sync(0xffffffffu, s, off);
        if (lane == 0) {
            out[0] = (float)(s / (double)B_TOTAL / (double)(2 * NPTS));
            g_ctr = 0;                  // reset for next graph replay
        }
    }
}

extern "C" void kernel_launch(void* const* d_in, const int* in_sizes, int n_in,
                              void* d_out, int out_size) {
    const float* inp = (const float*)d_in[0];   // "input"
    const float* tgt = (const float*)d_in[1];   // "targets"
    match_kernel<<<B_TOTAL, 32>>>(inp, tgt, (float*)d_out);
}